// round 2
// baseline (speedup 1.0000x reference)
#include <cuda_runtime.h>

// Problem constants
#define NP    64     // B*NUM_PARTS = 16*4
#define PC    32     // channels per part
#define HH    64
#define WW    512

typedef unsigned long long u64;

__device__ __forceinline__ u64 pk2(float a, float b) {
    u64 r; asm("mov.b64 %0, {%1,%2};" : "=l"(r) : "f"(a), "f"(b)); return r;
}
__device__ __forceinline__ void upk2(u64 v, float& a, float& b) {
    asm("mov.b64 {%0,%1}, %2;" : "=f"(a), "=f"(b) : "l"(v));
}
__device__ __forceinline__ void ffma2(u64& d, u64 a, u64 b) {
    asm("fma.rn.f32x2 %0, %1, %2, %0;" : "+l"(d) : "l"(a), "l"(b));
}

// fast sigmoid: odd Taylor poly valid to ~2e-5 for |t|<1, expf fallback otherwise
__device__ __forceinline__ float sigf(float t) {
    float t2 = t * t;
    float p = 0.5f + t * (0.25f + t2 * (-2.0833333e-2f + t2 * (2.0833333e-3f + t2 * (-2.1081349e-4f))));
    if (fabsf(t) >= 1.0f) p = 1.0f / (1.0f + __expf(-t));
    return p;
}

// Scratch (device globals, allocation-free)
__device__ float g_havg[NP * PC * HH];
__device__ float g_hmax[NP * PC * HH];
__device__ float g_wavg[NP * PC * WW];
__device__ float g_wmax[NP * PC * WW];
__device__ float g_ph[NP * PC * HH];
__device__ float g_pw[NP * PC * WW];

// ---------------------------------------------------------------------------
// K1: per-(n,c) slice stats: row(W) mean/max -> havg/hmax, col(H) mean/max -> wavg/wmax
// grid 2048, 256 threads
// ---------------------------------------------------------------------------
__global__ __launch_bounds__(256) void k1_stats(const float* __restrict__ x) {
    const int nc  = blockIdx.x;
    const int tid = threadIdx.x;
    const int r2  = tid >> 7;        // 0/1: which row of a 2-row stripe
    const int c4  = tid & 127;       // float4 column 0..127

    const float4* xs = reinterpret_cast<const float4*>(x + (size_t)nc * HH * WW);

    __shared__ float rs[HH][4], rm[HH][4];
    __shared__ float csh[WW], cmh[WW];

    float cs0 = 0.f, cs1 = 0.f, cs2 = 0.f, cs3 = 0.f;
    float cm0 = -3.4e38f, cm1 = -3.4e38f, cm2 = -3.4e38f, cm3 = -3.4e38f;
    const int wq = (tid >> 5) & 3;

    for (int h0 = 0; h0 < HH; h0 += 2) {
        const int h = h0 + r2;
        float4 v = xs[h * 128 + c4];
        cs0 += v.x; cs1 += v.y; cs2 += v.z; cs3 += v.w;
        cm0 = fmaxf(cm0, v.x); cm1 = fmaxf(cm1, v.y);
        cm2 = fmaxf(cm2, v.z); cm3 = fmaxf(cm3, v.w);
        float s = v.x + v.y + v.z + v.w;
        float m = fmaxf(fmaxf(v.x, v.y), fmaxf(v.z, v.w));
        #pragma unroll
        for (int off = 16; off >= 1; off >>= 1) {
            s += __shfl_xor_sync(0xffffffffu, s, off);
            m  = fmaxf(m, __shfl_xor_sync(0xffffffffu, m, off));
        }
        if ((tid & 31) == 0) { rs[h][wq] = s; rm[h][wq] = m; }
    }
    __syncthreads();

    if (tid < HH) {
        float s = rs[tid][0] + rs[tid][1] + rs[tid][2] + rs[tid][3];
        float m = fmaxf(fmaxf(rm[tid][0], rm[tid][1]), fmaxf(rm[tid][2], rm[tid][3]));
        g_havg[nc * HH + tid] = s * (1.0f / (float)WW);
        g_hmax[nc * HH + tid] = m;
    }

    if (r2 == 0) {
        csh[c4 * 4 + 0] = cs0; csh[c4 * 4 + 1] = cs1; csh[c4 * 4 + 2] = cs2; csh[c4 * 4 + 3] = cs3;
        cmh[c4 * 4 + 0] = cm0; cmh[c4 * 4 + 1] = cm1; cmh[c4 * 4 + 2] = cm2; cmh[c4 * 4 + 3] = cm3;
    }
    __syncthreads();
    if (r2 == 1) {
        const int w = c4 * 4;
        g_wavg[nc * WW + w + 0] = (cs0 + csh[w + 0]) * (1.0f / (float)HH);
        g_wavg[nc * WW + w + 1] = (cs1 + csh[w + 1]) * (1.0f / (float)HH);
        g_wavg[nc * WW + w + 2] = (cs2 + csh[w + 2]) * (1.0f / (float)HH);
        g_wavg[nc * WW + w + 3] = (cs3 + csh[w + 3]) * (1.0f / (float)HH);
        g_wmax[nc * WW + w + 0] = fmaxf(cm0, cmh[w + 0]);
        g_wmax[nc * WW + w + 1] = fmaxf(cm1, cmh[w + 1]);
        g_wmax[nc * WW + w + 2] = fmaxf(cm2, cmh[w + 2]);
        g_wmax[nc * WW + w + 3] = fmaxf(cm3, cmh[w + 3]);
    }
}

// ---------------------------------------------------------------------------
// K2: ph conv (3x2, pad h=1) + relu + softmax over h. grid 64 (per n), 256 thr
// ---------------------------------------------------------------------------
__global__ __launch_bounds__(256) void k2_ph(const float* __restrict__ w_h,
                                             const float* __restrict__ b_h) {
    const int n   = blockIdx.x;
    const int tid = threadIdx.x;

    __shared__ float ha[PC][HH], hm[PC][HH];
    __shared__ float wh[PC * PC * 6];

    for (int idx = tid; idx < PC * HH; idx += 256) {
        ha[idx >> 6][idx & 63] = g_havg[n * PC * HH + idx];
        hm[idx >> 6][idx & 63] = g_hmax[n * PC * HH + idx];
    }
    for (int idx = tid; idx < PC * PC * 6; idx += 256) wh[idx] = w_h[idx];
    __syncthreads();

    const int o  = tid >> 3;     // 0..31
    const int j  = tid & 7;      // 8 threads per o, 8 h each
    const int hb = j * 8;

    float acc[8];
    const float bo = b_h[o];
    #pragma unroll
    for (int t = 0; t < 8; t++) acc[t] = bo;

    for (int i = 0; i < PC; i++) {
        const float* wp = &wh[(o * PC + i) * 6];
        const float w00 = wp[0], w01 = wp[1], w10 = wp[2], w11 = wp[3], w20 = wp[4], w21 = wp[5];
        float wA[10], wM[10];
        wA[0] = (hb > 0) ? ha[i][hb - 1] : 0.f;
        wM[0] = (hb > 0) ? hm[i][hb - 1] : 0.f;
        #pragma unroll
        for (int t = 0; t < 8; t++) { wA[t + 1] = ha[i][hb + t]; wM[t + 1] = hm[i][hb + t]; }
        wA[9] = (hb + 8 < HH) ? ha[i][hb + 8] : 0.f;
        wM[9] = (hb + 8 < HH) ? hm[i][hb + 8] : 0.f;
        #pragma unroll
        for (int t = 0; t < 8; t++) {
            acc[t] += wA[t] * w00 + wM[t] * w01
                    + wA[t + 1] * w10 + wM[t + 1] * w11
                    + wA[t + 2] * w20 + wM[t + 2] * w21;
        }
    }

    // relu + softmax over the 64 h values (8-lane group)
    float lm = -3.4e38f;
    #pragma unroll
    for (int t = 0; t < 8; t++) { acc[t] = fmaxf(acc[t], 0.f); lm = fmaxf(lm, acc[t]); }
    #pragma unroll
    for (int off = 1; off <= 4; off <<= 1) lm = fmaxf(lm, __shfl_xor_sync(0xffffffffu, lm, off));
    float ls = 0.f;
    #pragma unroll
    for (int t = 0; t < 8; t++) { acc[t] = __expf(acc[t] - lm); ls += acc[t]; }
    #pragma unroll
    for (int off = 1; off <= 4; off <<= 1) ls += __shfl_xor_sync(0xffffffffu, ls, off);
    const float inv = 1.0f / ls;
    #pragma unroll
    for (int t = 0; t < 8; t++) g_ph[(n * PC + o) * HH + hb + t] = acc[t] * inv;
}

// ---------------------------------------------------------------------------
// K3: pw conv (2x3, pad w=1) + relu + softmax over w. grid 64 (per n), 512 thr
// dynamic smem: wavg[32][512] + wmax[32][512] + weights (152 KB)
// ---------------------------------------------------------------------------
__global__ __launch_bounds__(512) void k3_pw(const float* __restrict__ w_w,
                                             const float* __restrict__ b_w) {
    extern __shared__ float sm3[];
    float* wa = sm3;                    // [32][512]
    float* wm = sm3 + PC * WW;          // [32][512]
    float* ww = sm3 + 2 * PC * WW;      // 6144

    const int n   = blockIdx.x;
    const int tid = threadIdx.x;

    for (int idx = tid; idx < PC * WW; idx += 512) {
        wa[idx] = g_wavg[n * PC * WW + idx];
        wm[idx] = g_wmax[n * PC * WW + idx];
    }
    for (int idx = tid; idx < PC * PC * 6; idx += 512) ww[idx] = w_w[idx];
    __syncthreads();

    const int o = tid >> 4;   // 0..31
    const int j = tid & 15;   // lane within 16-thread group; w groups j*4 + 64k

    float acc[32];
    const float bo = b_w[o];
    #pragma unroll
    for (int t = 0; t < 32; t++) acc[t] = bo;

    for (int i = 0; i < PC; i++) {
        const float* wp = &ww[(o * PC + i) * 6];
        const float a0 = wp[0], a1 = wp[1], a2 = wp[2];   // kh=0 (avg), kw 0..2
        const float m0 = wp[3], m1 = wp[4], m2 = wp[5];   // kh=1 (max), kw 0..2
        const float* A = wa + i * WW;
        const float* M = wm + i * WW;
        #pragma unroll
        for (int k = 0; k < 8; k++) {
            const int w0 = j * 4 + k * 64;
            float4 av = *reinterpret_cast<const float4*>(&A[w0]);
            float4 mv = *reinterpret_cast<const float4*>(&M[w0]);
            float am1 = (w0 > 0) ? A[w0 - 1] : 0.f;
            float mm1 = (w0 > 0) ? M[w0 - 1] : 0.f;
            float ap4 = (w0 + 4 < WW) ? A[w0 + 4] : 0.f;
            float mp4 = (w0 + 4 < WW) ? M[w0 + 4] : 0.f;
            acc[k*4+0] += am1 * a0 + av.x * a1 + av.y * a2 + mm1 * m0 + mv.x * m1 + mv.y * m2;
            acc[k*4+1] += av.x * a0 + av.y * a1 + av.z * a2 + mv.x * m0 + mv.y * m1 + mv.z * m2;
            acc[k*4+2] += av.y * a0 + av.z * a1 + av.w * a2 + mv.y * m0 + mv.z * m1 + mv.w * m2;
            acc[k*4+3] += av.z * a0 + av.w * a1 + ap4 * a2 + mv.z * m0 + mv.w * m1 + mp4 * m2;
        }
    }

    // relu + softmax over all 512 w (16-lane group)
    float lm = -3.4e38f;
    #pragma unroll
    for (int t = 0; t < 32; t++) { acc[t] = fmaxf(acc[t], 0.f); lm = fmaxf(lm, acc[t]); }
    #pragma unroll
    for (int off = 1; off <= 8; off <<= 1) lm = fmaxf(lm, __shfl_xor_sync(0xffffffffu, lm, off));
    float ls = 0.f;
    #pragma unroll
    for (int t = 0; t < 32; t++) { acc[t] = __expf(acc[t] - lm); ls += acc[t]; }
    #pragma unroll
    for (int off = 1; off <= 8; off <<= 1) ls += __shfl_xor_sync(0xffffffffu, ls, off);
    const float inv = 1.0f / ls;

    float* dst = g_pw + (n * PC + o) * WW;
    #pragma unroll
    for (int k = 0; k < 8; k++) {
        const int w0 = j * 4 + k * 64;
        float4 r;
        r.x = acc[k*4+0] * inv; r.y = acc[k*4+1] * inv;
        r.z = acc[k*4+2] * inv; r.w = acc[k*4+3] * inv;
        *reinterpret_cast<float4*>(&dst[w0]) = r;
    }
}

// ---------------------------------------------------------------------------
// K4: apply. One CTA per (n,h): amap[o,w] = At[:,o] . pw[:,w]; out = x*(1+sig)
// 256 threads, lane->o-tile (pw LDS broadcast), f32x2 packed FMA
// dynamic smem: pw[32][512] (64KB) + At[32][32] (4KB)
// ---------------------------------------------------------------------------
__global__ __launch_bounds__(256) void k4_apply(const float* __restrict__ x,
                                                const float* __restrict__ w_e,
                                                const float* __restrict__ b_e,
                                                float* __restrict__ out) {
    extern __shared__ float sm4[];
    float* pws = sm4;            // [32][512]
    float* At  = sm4 + PC * WW;  // [c][o]
    __shared__ float phs[PC];

    const int bid = blockIdx.x;
    const int n   = bid >> 6;
    const int h   = bid & 63;
    const int tid = threadIdx.x;

    const float4* pwg = reinterpret_cast<const float4*>(g_pw + n * PC * WW);
    float4* pw4 = reinterpret_cast<float4*>(pws);
    for (int idx = tid; idx < PC * WW / 4; idx += 256) pw4[idx] = pwg[idx];
    if (tid < PC) phs[tid] = g_ph[(n * PC + tid) * HH + h];
    __syncthreads();

    for (int idx = tid; idx < PC * PC; idx += 256) {
        const int c = idx >> 5, o = idx & 31;
        At[idx] = w_e[o * PC + c] * phs[c];
    }
    __syncthreads();

    const int ot = tid & 7;      // o-tile (varies fastest -> pw broadcast per phase)
    const int wt = tid >> 3;     // w-tile 0..31
    const int o0 = ot * 4;
    const int w0 = wt * 16;

    u64 acc[4][8];
    #pragma unroll
    for (int oi = 0; oi < 4; oi++)
        #pragma unroll
        for (int wj = 0; wj < 8; wj++) acc[oi][wj] = 0ull;

    #pragma unroll 4
    for (int c = 0; c < PC; c++) {
        const float4 a = *reinterpret_cast<const float4*>(&At[c * PC + o0]);
        u64 av[4];
        av[0] = pk2(a.x, a.x); av[1] = pk2(a.y, a.y);
        av[2] = pk2(a.z, a.z); av[3] = pk2(a.w, a.w);
        const ulonglong2* pr = reinterpret_cast<const ulonglong2*>(&pws[c * WW + w0]);
        ulonglong2 q0 = pr[0], q1 = pr[1], q2 = pr[2], q3 = pr[3];
        u64 pp[8] = {q0.x, q0.y, q1.x, q1.y, q2.x, q2.y, q3.x, q3.y};
        #pragma unroll
        for (int oi = 0; oi < 4; oi++)
            #pragma unroll
            for (int wj = 0; wj < 8; wj++)
                ffma2(acc[oi][wj], av[oi], pp[wj]);
    }

    #pragma unroll
    for (int oi = 0; oi < 4; oi++) {
        const int o = o0 + oi;
        const float bias = b_e[o];
        const size_t base = (((size_t)(n * PC + o)) * HH + h) * WW + w0;
        const float4* xin = reinterpret_cast<const float4*>(x + base);
        float4* op = reinterpret_cast<float4*>(out + base);
        #pragma unroll
        for (int q = 0; q < 4; q++) {
            float4 xv = xin[q];
            float t0, t1, t2, t3;
            upk2(acc[oi][2 * q],     t0, t1);
            upk2(acc[oi][2 * q + 1], t2, t3);
            float4 r;
            r.x = xv.x * (1.0f + sigf(t0 + bias));
            r.y = xv.y * (1.0f + sigf(t1 + bias));
            r.z = xv.z * (1.0f + sigf(t2 + bias));
            r.w = xv.w * (1.0f + sigf(t3 + bias));
            op[q] = r;
        }
    }
}

extern "C" void kernel_launch(void* const* d_in, const int* in_sizes, int n_in,
                              void* d_out, int out_size) {
    const float* x   = (const float*)d_in[0];
    const float* w_h = (const float*)d_in[1];
    const float* b_h = (const float*)d_in[2];
    const float* w_w = (const float*)d_in[3];
    const float* b_w = (const float*)d_in[4];
    const float* w_e = (const float*)d_in[5];
    const float* b_e = (const float*)d_in[6];
    float* out = (float*)d_out;

    const int smem3 = (2 * PC * WW + PC * PC * 6) * 4;   // 155648
    const int smem4 = (PC * WW + PC * PC) * 4;           // 69632
    cudaFuncSetAttribute(k3_pw,    cudaFuncAttributeMaxDynamicSharedMemorySize, smem3);
    cudaFuncSetAttribute(k4_apply, cudaFuncAttributeMaxDynamicSharedMemorySize, smem4);

    k1_stats<<<NP * PC, 256>>>(x);
    k2_ph<<<NP, 256>>>(w_h, b_h);
    k3_pw<<<NP, 512, smem3>>>(w_w, b_w);
    k4_apply<<<NP * HH, 256, smem4>>>(x, w_e, b_e, out);
}

// round 3
// speedup vs baseline: 1.6061x; 1.6061x over previous
#include <cuda_runtime.h>

// Problem constants
#define NP    64     // B*NUM_PARTS = 16*4
#define PC    32     // channels per part
#define HH    64
#define WW    512

typedef unsigned long long u64;

__device__ __forceinline__ u64 pk2(float a, float b) {
    u64 r; asm("mov.b64 %0, {%1,%2};" : "=l"(r) : "f"(a), "f"(b)); return r;
}
__device__ __forceinline__ void upk2(u64 v, float& a, float& b) {
    asm("mov.b64 {%0,%1}, %2;" : "=f"(a), "=f"(b) : "l"(v));
}
__device__ __forceinline__ void ffma2(u64& d, u64 a, u64 b) {
    asm("fma.rn.f32x2 %0, %1, %2, %0;" : "+l"(d) : "l"(a), "l"(b));
}

// fast sigmoid: odd Taylor poly valid to ~2e-5 for |t|<1, expf fallback otherwise
__device__ __forceinline__ float sigf(float t) {
    float t2 = t * t;
    float p = 0.5f + t * (0.25f + t2 * (-2.0833333e-2f + t2 * (2.0833333e-3f + t2 * (-2.1081349e-4f))));
    if (fabsf(t) >= 1.0f) p = 1.0f / (1.0f + __expf(-t));
    return p;
}

// Scratch (device globals, allocation-free)
__device__ float g_havg[NP * PC * HH];
__device__ float g_hmax[NP * PC * HH];
__device__ float g_wavg[NP * PC * WW];
__device__ float g_wmax[NP * PC * WW];
__device__ float g_ph[NP * PC * HH];
__device__ float g_pw[NP * PC * WW];

// ---------------------------------------------------------------------------
// K1: per-(n,c) slice stats. Quad-level shfl reduce + smem partials.
// grid 2048, 256 threads
// ---------------------------------------------------------------------------
__global__ __launch_bounds__(256) void k1_stats(const float* __restrict__ x) {
    const int nc  = blockIdx.x;
    const int tid = threadIdx.x;
    const int r2  = tid >> 7;        // 0/1: which row of a 2-row stripe
    const int c4  = tid & 127;       // float4 column 0..127

    const float4* xs = reinterpret_cast<const float4*>(x + (size_t)nc * HH * WW);

    __shared__ float rs[HH][33], rm[HH][33];   // 33: kill final-reduce bank conflict
    __shared__ float csh[WW], cmh[WW];

    float cs0 = 0.f, cs1 = 0.f, cs2 = 0.f, cs3 = 0.f;
    float cm0 = -3.4e38f, cm1 = -3.4e38f, cm2 = -3.4e38f, cm3 = -3.4e38f;
    const int q = c4 >> 2;

    for (int h0 = 0; h0 < HH; h0 += 2) {
        const int h = h0 + r2;
        float4 v = xs[h * 128 + c4];
        cs0 += v.x; cs1 += v.y; cs2 += v.z; cs3 += v.w;
        cm0 = fmaxf(cm0, v.x); cm1 = fmaxf(cm1, v.y);
        cm2 = fmaxf(cm2, v.z); cm3 = fmaxf(cm3, v.w);
        float s = (v.x + v.y) + (v.z + v.w);
        float m = fmaxf(fmaxf(v.x, v.y), fmaxf(v.z, v.w));
        s += __shfl_xor_sync(0xffffffffu, s, 1);
        m  = fmaxf(m, __shfl_xor_sync(0xffffffffu, m, 1));
        s += __shfl_xor_sync(0xffffffffu, s, 2);
        m  = fmaxf(m, __shfl_xor_sync(0xffffffffu, m, 2));
        if ((tid & 3) == 0) { rs[h][q] = s; rm[h][q] = m; }
    }
    __syncthreads();

    if (tid < HH) {
        float s = 0.f, m = -3.4e38f;
        #pragma unroll
        for (int k = 0; k < 32; k++) { s += rs[tid][k]; m = fmaxf(m, rm[tid][k]); }
        g_havg[nc * HH + tid] = s * (1.0f / (float)WW);
        g_hmax[nc * HH + tid] = m;
    }

    if (r2 == 0) {
        csh[c4 * 4 + 0] = cs0; csh[c4 * 4 + 1] = cs1; csh[c4 * 4 + 2] = cs2; csh[c4 * 4 + 3] = cs3;
        cmh[c4 * 4 + 0] = cm0; cmh[c4 * 4 + 1] = cm1; cmh[c4 * 4 + 2] = cm2; cmh[c4 * 4 + 3] = cm3;
    }
    __syncthreads();
    if (r2 == 1) {
        const int w = c4 * 4;
        g_wavg[nc * WW + w + 0] = (cs0 + csh[w + 0]) * (1.0f / (float)HH);
        g_wavg[nc * WW + w + 1] = (cs1 + csh[w + 1]) * (1.0f / (float)HH);
        g_wavg[nc * WW + w + 2] = (cs2 + csh[w + 2]) * (1.0f / (float)HH);
        g_wavg[nc * WW + w + 3] = (cs3 + csh[w + 3]) * (1.0f / (float)HH);
        g_wmax[nc * WW + w + 0] = fmaxf(cm0, cmh[w + 0]);
        g_wmax[nc * WW + w + 1] = fmaxf(cm1, cmh[w + 1]);
        g_wmax[nc * WW + w + 2] = fmaxf(cm2, cmh[w + 2]);
        g_wmax[nc * WW + w + 3] = fmaxf(cm3, cmh[w + 3]);
    }
}

// ---------------------------------------------------------------------------
// K23: merged ph conv (blocks [0,64)) + pw conv (blocks [64,320), o split 4-way)
// 256 threads. dynamic smem: k3-part needs 34304 floats = 137216 B
// ---------------------------------------------------------------------------
__global__ __launch_bounds__(256) void k23(const float* __restrict__ w_h,
                                           const float* __restrict__ b_h,
                                           const float* __restrict__ w_w,
                                           const float* __restrict__ b_w) {
    extern __shared__ float sm[];
    const int bid = blockIdx.x;
    const int tid = threadIdx.x;

    if (bid < 64) {
        // ---------------- ph: conv 3x2 pad(h)=1 + relu + softmax over h ----
        const int n = bid;
        float* ha = sm;                 // [32][64]
        float* hm = sm + PC * HH;       // [32][64]
        float* wh = sm + 2 * PC * HH;   // 6144

        for (int idx = tid; idx < PC * HH; idx += 256) {
            ha[idx] = g_havg[n * PC * HH + idx];
            hm[idx] = g_hmax[n * PC * HH + idx];
        }
        for (int idx = tid; idx < PC * PC * 6; idx += 256) wh[idx] = w_h[idx];
        __syncthreads();

        const int o  = tid >> 3;     // 0..31
        const int j  = tid & 7;      // 8 threads per o, 8 h each
        const int hb = j * 8;

        float acc[8];
        const float bo = b_h[o];
        #pragma unroll
        for (int t = 0; t < 8; t++) acc[t] = bo;

        for (int i = 0; i < PC; i++) {
            const float* wp = &wh[(o * PC + i) * 6];
            const float w00 = wp[0], w01 = wp[1], w10 = wp[2], w11 = wp[3], w20 = wp[4], w21 = wp[5];
            const float* A = ha + i * HH;
            const float* M = hm + i * HH;
            float wA[10], wM[10];
            wA[0] = (hb > 0) ? A[hb - 1] : 0.f;
            wM[0] = (hb > 0) ? M[hb - 1] : 0.f;
            #pragma unroll
            for (int t = 0; t < 8; t++) { wA[t + 1] = A[hb + t]; wM[t + 1] = M[hb + t]; }
            wA[9] = (hb + 8 < HH) ? A[hb + 8] : 0.f;
            wM[9] = (hb + 8 < HH) ? M[hb + 8] : 0.f;
            #pragma unroll
            for (int t = 0; t < 8; t++) {
                acc[t] += wA[t] * w00 + wM[t] * w01
                        + wA[t + 1] * w10 + wM[t + 1] * w11
                        + wA[t + 2] * w20 + wM[t + 2] * w21;
            }
        }

        float lm = -3.4e38f;
        #pragma unroll
        for (int t = 0; t < 8; t++) { acc[t] = fmaxf(acc[t], 0.f); lm = fmaxf(lm, acc[t]); }
        #pragma unroll
        for (int off = 1; off <= 4; off <<= 1) lm = fmaxf(lm, __shfl_xor_sync(0xffffffffu, lm, off));
        float ls = 0.f;
        #pragma unroll
        for (int t = 0; t < 8; t++) { acc[t] = __expf(acc[t] - lm); ls += acc[t]; }
        #pragma unroll
        for (int off = 1; off <= 4; off <<= 1) ls += __shfl_xor_sync(0xffffffffu, ls, off);
        const float inv = 1.0f / ls;
        #pragma unroll
        for (int t = 0; t < 8; t++) g_ph[(n * PC + o) * HH + hb + t] = acc[t] * inv;
    } else {
        // ---------------- pw: conv 2x3 pad(w)=1 + relu + softmax over w ----
        const int b2 = bid - 64;
        const int n  = b2 >> 2;
        const int og = b2 & 3;          // o group of 8

        float* wa = sm;                  // [32][512]
        float* wm = sm + PC * WW;        // [32][512]
        float* ww = sm + 2 * PC * WW;    // 8*32*6 = 1536

        {
            const float4* sa = reinterpret_cast<const float4*>(g_wavg + n * PC * WW);
            const float4* sx = reinterpret_cast<const float4*>(g_wmax + n * PC * WW);
            float4* da = reinterpret_cast<float4*>(wa);
            float4* dm = reinterpret_cast<float4*>(wm);
            for (int idx = tid; idx < PC * WW / 4; idx += 256) { da[idx] = sa[idx]; dm[idx] = sx[idx]; }
        }
        {
            const float* src = w_w + og * 8 * PC * 6;
            for (int idx = tid; idx < 8 * PC * 6; idx += 256) ww[idx] = src[idx];
        }
        __syncthreads();

        const int oo = tid >> 5;            // 0..7 within group
        const int o  = og * 8 + oo;
        const int j  = tid & 31;            // one warp per o

        float acc[16];
        const float bo = b_w[o];
        #pragma unroll
        for (int t = 0; t < 16; t++) acc[t] = bo;

        for (int i = 0; i < PC; i++) {
            const float* wp = &ww[(oo * PC + i) * 6];
            const float a0 = wp[0], a1 = wp[1], a2 = wp[2];
            const float m0 = wp[3], m1 = wp[4], m2 = wp[5];
            const float* A = wa + i * WW;
            const float* M = wm + i * WW;
            #pragma unroll
            for (int k = 0; k < 4; k++) {
                const int w0 = j * 4 + k * 128;
                float4 av = *reinterpret_cast<const float4*>(&A[w0]);
                float4 mv = *reinterpret_cast<const float4*>(&M[w0]);
                float am1 = (w0 > 0) ? A[w0 - 1] : 0.f;
                float mm1 = (w0 > 0) ? M[w0 - 1] : 0.f;
                float ap4 = (w0 + 4 < WW) ? A[w0 + 4] : 0.f;
                float mp4 = (w0 + 4 < WW) ? M[w0 + 4] : 0.f;
                acc[k*4+0] += am1 * a0 + av.x * a1 + av.y * a2 + mm1 * m0 + mv.x * m1 + mv.y * m2;
                acc[k*4+1] += av.x * a0 + av.y * a1 + av.z * a2 + mv.x * m0 + mv.y * m1 + mv.z * m2;
                acc[k*4+2] += av.y * a0 + av.z * a1 + av.w * a2 + mv.y * m0 + mv.z * m1 + mv.w * m2;
                acc[k*4+3] += av.z * a0 + av.w * a1 + ap4 * a2 + mv.z * m0 + mv.w * m1 + mp4 * m2;
            }
        }

        float lm = -3.4e38f;
        #pragma unroll
        for (int t = 0; t < 16; t++) { acc[t] = fmaxf(acc[t], 0.f); lm = fmaxf(lm, acc[t]); }
        #pragma unroll
        for (int off = 1; off <= 16; off <<= 1) lm = fmaxf(lm, __shfl_xor_sync(0xffffffffu, lm, off));
        float ls = 0.f;
        #pragma unroll
        for (int t = 0; t < 16; t++) { acc[t] = __expf(acc[t] - lm); ls += acc[t]; }
        #pragma unroll
        for (int off = 1; off <= 16; off <<= 1) ls += __shfl_xor_sync(0xffffffffu, ls, off);
        const float inv = 1.0f / ls;

        float* dst = g_pw + (n * PC + o) * WW;
        #pragma unroll
        for (int k = 0; k < 4; k++) {
            const int w0 = j * 4 + k * 128;
            float4 r;
            r.x = acc[k*4+0] * inv; r.y = acc[k*4+1] * inv;
            r.z = acc[k*4+2] * inv; r.w = acc[k*4+3] * inv;
            *reinterpret_cast<float4*>(&dst[w0]) = r;
        }
    }
}

// ---------------------------------------------------------------------------
// K4: apply. One CTA per (n, h-block of 8). pw staged ONCE, At precomputed
// for all 8 h, then h-loop reuses tile. 256 threads, f32x2 packed FMA.
// dynamic smem: pw[32][512] (64KB) + At8[8][32][32] (32KB) = 98304 B
// ---------------------------------------------------------------------------
__global__ __launch_bounds__(256) void k4_apply(const float* __restrict__ x,
                                                const float* __restrict__ w_e,
                                                const float* __restrict__ b_e,
                                                float* __restrict__ out) {
    extern __shared__ float sm4[];
    float* pws = sm4;            // [32][512]
    float* At8 = sm4 + PC * WW;  // [8][c][o]
    __shared__ float phs[8 * PC];

    const int bid = blockIdx.x;
    const int n   = bid >> 3;
    const int hb  = bid & 7;     // h block: h = hb*8 + hl
    const int tid = threadIdx.x;

    const float4* pwg = reinterpret_cast<const float4*>(g_pw + n * PC * WW);
    float4* pw4 = reinterpret_cast<float4*>(pws);
    for (int idx = tid; idx < PC * WW / 4; idx += 256) pw4[idx] = pwg[idx];
    {
        const int hl = tid >> 5, c = tid & 31;   // 256 = 8*32 exactly
        phs[tid] = g_ph[(n * PC + c) * HH + hb * 8 + hl];
    }
    __syncthreads();

    for (int idx = tid; idx < 8 * PC * PC; idx += 256) {
        const int hl = idx >> 10;
        const int c  = (idx >> 5) & 31;
        const int o  = idx & 31;
        At8[idx] = w_e[o * PC + c] * phs[hl * PC + c];
    }
    __syncthreads();

    const int ot = tid & 7;      // o-tile (varies fastest -> pw broadcast per phase)
    const int wt = tid >> 3;     // w-tile 0..31
    const int o0 = ot * 4;
    const int w0 = wt * 16;

    const float4 be = *reinterpret_cast<const float4*>(&b_e[o0]);
    const u64 binit[4] = { pk2(be.x, be.x), pk2(be.y, be.y), pk2(be.z, be.z), pk2(be.w, be.w) };

    #pragma unroll 1
    for (int hl = 0; hl < 8; hl++) {
        const int h = hb * 8 + hl;
        const float* At = At8 + hl * (PC * PC);

        u64 acc[4][8];
        #pragma unroll
        for (int oi = 0; oi < 4; oi++)
            #pragma unroll
            for (int wj = 0; wj < 8; wj++) acc[oi][wj] = binit[oi];

        #pragma unroll 4
        for (int c = 0; c < PC; c++) {
            const float4 a = *reinterpret_cast<const float4*>(&At[c * PC + o0]);
            u64 av[4];
            av[0] = pk2(a.x, a.x); av[1] = pk2(a.y, a.y);
            av[2] = pk2(a.z, a.z); av[3] = pk2(a.w, a.w);
            const ulonglong2* pr = reinterpret_cast<const ulonglong2*>(&pws[c * WW + w0]);
            ulonglong2 q0 = pr[0], q1 = pr[1], q2 = pr[2], q3 = pr[3];
            u64 pp[8] = {q0.x, q0.y, q1.x, q1.y, q2.x, q2.y, q3.x, q3.y};
            #pragma unroll
            for (int oi = 0; oi < 4; oi++)
                #pragma unroll
                for (int wj = 0; wj < 8; wj++)
                    ffma2(acc[oi][wj], av[oi], pp[wj]);
        }

        #pragma unroll
        for (int oi = 0; oi < 4; oi++) {
            const int o = o0 + oi;
            const size_t base = (((size_t)(n * PC + o)) * HH + h) * WW + w0;
            const float4* xin = reinterpret_cast<const float4*>(x + base);
            float4* op = reinterpret_cast<float4*>(out + base);
            #pragma unroll
            for (int q = 0; q < 4; q++) {
                float4 xv = xin[q];
                float t0, t1, t2, t3;
                upk2(acc[oi][2 * q],     t0, t1);
                upk2(acc[oi][2 * q + 1], t2, t3);
                float4 r;
                r.x = xv.x * (1.0f + sigf(t0));
                r.y = xv.y * (1.0f + sigf(t1));
                r.z = xv.z * (1.0f + sigf(t2));
                r.w = xv.w * (1.0f + sigf(t3));
                op[q] = r;
            }
        }
    }
}

extern "C" void kernel_launch(void* const* d_in, const int* in_sizes, int n_in,
                              void* d_out, int out_size) {
    const float* x   = (const float*)d_in[0];
    const float* w_h = (const float*)d_in[1];
    const float* b_h = (const float*)d_in[2];
    const float* w_w = (const float*)d_in[3];
    const float* b_w = (const float*)d_in[4];
    const float* w_e = (const float*)d_in[5];
    const float* b_e = (const float*)d_in[6];
    float* out = (float*)d_out;

    const int smem23 = (2 * PC * WW + 8 * PC * 6) * 4;   // 137216
    const int smem4  = (PC * WW + 8 * PC * PC) * 4;      // 98304
    cudaFuncSetAttribute(k23,      cudaFuncAttributeMaxDynamicSharedMemorySize, smem23);
    cudaFuncSetAttribute(k4_apply, cudaFuncAttributeMaxDynamicSharedMemorySize, smem4);

    k1_stats<<<NP * PC, 256>>>(x);
    k23<<<64 + NP * 4, 256, smem23>>>(w_h, b_h, w_w, b_w);
    k4_apply<<<NP * 8, 256, smem4>>>(x, w_e, b_e, out);
}

// round 4
// speedup vs baseline: 1.6727x; 1.0415x over previous
#include <cuda_runtime.h>

// Problem constants
#define NP    64     // B*NUM_PARTS = 16*4
#define PC    32     // channels per part
#define HH    64
#define WW    512
#define HB    4      // h rows per K4 CTA
#define WH    256    // w half width per K4 CTA

typedef unsigned long long u64;

__device__ __forceinline__ u64 pk2(float a, float b) {
    u64 r; asm("mov.b64 %0, {%1,%2};" : "=l"(r) : "f"(a), "f"(b)); return r;
}
__device__ __forceinline__ void upk2(u64 v, float& a, float& b) {
    asm("mov.b64 {%0,%1}, %2;" : "=f"(a), "=f"(b) : "l"(v));
}
__device__ __forceinline__ void ffma2(u64& d, u64 a, u64 b) {
    asm("fma.rn.f32x2 %0, %1, %2, %0;" : "+l"(d) : "l"(a), "l"(b));
}

// branchless sigmoid: 2 MUFU ops, no divergence, ~2^-21 accuracy
__device__ __forceinline__ float sigf(float t) {
    float e = __expf(-fabsf(t));
    float s = __fdividef(1.0f, 1.0f + e);   // sigmoid(|t|)
    return (t >= 0.0f) ? s : 1.0f - s;
}

// Scratch (device globals, allocation-free)
__device__ float g_havg[NP * PC * HH];
__device__ float g_hmax[NP * PC * HH];
__device__ float g_wavg[NP * PC * WW];
__device__ float g_wmax[NP * PC * WW];
__device__ float g_ph[NP * PC * HH];
__device__ float g_pw[NP * PC * WW];

// ---------------------------------------------------------------------------
// K1: per-(n,c) slice stats. Quad-level shfl reduce + smem partials.
// grid 2048, 256 threads
// ---------------------------------------------------------------------------
__global__ __launch_bounds__(256) void k1_stats(const float* __restrict__ x) {
    const int nc  = blockIdx.x;
    const int tid = threadIdx.x;
    const int r2  = tid >> 7;        // 0/1: which row of a 2-row stripe
    const int c4  = tid & 127;       // float4 column 0..127

    const float4* xs = reinterpret_cast<const float4*>(x + (size_t)nc * HH * WW);

    __shared__ float rs[HH][33], rm[HH][33];   // 33: kill final-reduce bank conflict
    __shared__ float csh[WW], cmh[WW];

    float cs0 = 0.f, cs1 = 0.f, cs2 = 0.f, cs3 = 0.f;
    float cm0 = -3.4e38f, cm1 = -3.4e38f, cm2 = -3.4e38f, cm3 = -3.4e38f;
    const int q = c4 >> 2;

    for (int h0 = 0; h0 < HH; h0 += 2) {
        const int h = h0 + r2;
        float4 v = xs[h * 128 + c4];
        cs0 += v.x; cs1 += v.y; cs2 += v.z; cs3 += v.w;
        cm0 = fmaxf(cm0, v.x); cm1 = fmaxf(cm1, v.y);
        cm2 = fmaxf(cm2, v.z); cm3 = fmaxf(cm3, v.w);
        float s = (v.x + v.y) + (v.z + v.w);
        float m = fmaxf(fmaxf(v.x, v.y), fmaxf(v.z, v.w));
        s += __shfl_xor_sync(0xffffffffu, s, 1);
        m  = fmaxf(m, __shfl_xor_sync(0xffffffffu, m, 1));
        s += __shfl_xor_sync(0xffffffffu, s, 2);
        m  = fmaxf(m, __shfl_xor_sync(0xffffffffu, m, 2));
        if ((tid & 3) == 0) { rs[h][q] = s; rm[h][q] = m; }
    }
    __syncthreads();

    if (tid < HH) {
        float s = 0.f, m = -3.4e38f;
        #pragma unroll
        for (int k = 0; k < 32; k++) { s += rs[tid][k]; m = fmaxf(m, rm[tid][k]); }
        g_havg[nc * HH + tid] = s * (1.0f / (float)WW);
        g_hmax[nc * HH + tid] = m;
    }

    if (r2 == 0) {
        csh[c4 * 4 + 0] = cs0; csh[c4 * 4 + 1] = cs1; csh[c4 * 4 + 2] = cs2; csh[c4 * 4 + 3] = cs3;
        cmh[c4 * 4 + 0] = cm0; cmh[c4 * 4 + 1] = cm1; cmh[c4 * 4 + 2] = cm2; cmh[c4 * 4 + 3] = cm3;
    }
    __syncthreads();
    if (r2 == 1) {
        const int w = c4 * 4;
        g_wavg[nc * WW + w + 0] = (cs0 + csh[w + 0]) * (1.0f / (float)HH);
        g_wavg[nc * WW + w + 1] = (cs1 + csh[w + 1]) * (1.0f / (float)HH);
        g_wavg[nc * WW + w + 2] = (cs2 + csh[w + 2]) * (1.0f / (float)HH);
        g_wavg[nc * WW + w + 3] = (cs3 + csh[w + 3]) * (1.0f / (float)HH);
        g_wmax[nc * WW + w + 0] = fmaxf(cm0, cmh[w + 0]);
        g_wmax[nc * WW + w + 1] = fmaxf(cm1, cmh[w + 1]);
        g_wmax[nc * WW + w + 2] = fmaxf(cm2, cmh[w + 2]);
        g_wmax[nc * WW + w + 3] = fmaxf(cm3, cmh[w + 3]);
    }
}

// ---------------------------------------------------------------------------
// K23: merged ph conv (blocks [0,64)) + pw conv (blocks [64,320), o split 4-way)
// 256 threads. dynamic smem: k3-part needs 34304 floats = 137216 B
// ---------------------------------------------------------------------------
__global__ __launch_bounds__(256) void k23(const float* __restrict__ w_h,
                                           const float* __restrict__ b_h,
                                           const float* __restrict__ w_w,
                                           const float* __restrict__ b_w) {
    extern __shared__ float sm[];
    const int bid = blockIdx.x;
    const int tid = threadIdx.x;

    if (bid < 64) {
        // ---------------- ph: conv 3x2 pad(h)=1 + relu + softmax over h ----
        const int n = bid;
        float* ha = sm;                 // [32][64]
        float* hm = sm + PC * HH;       // [32][64]
        float* wh = sm + 2 * PC * HH;   // 6144

        for (int idx = tid; idx < PC * HH; idx += 256) {
            ha[idx] = g_havg[n * PC * HH + idx];
            hm[idx] = g_hmax[n * PC * HH + idx];
        }
        for (int idx = tid; idx < PC * PC * 6; idx += 256) wh[idx] = w_h[idx];
        __syncthreads();

        const int o  = tid >> 3;     // 0..31
        const int j  = tid & 7;      // 8 threads per o, 8 h each
        const int hb = j * 8;

        float acc[8];
        const float bo = b_h[o];
        #pragma unroll
        for (int t = 0; t < 8; t++) acc[t] = bo;

        for (int i = 0; i < PC; i++) {
            const float* wp = &wh[(o * PC + i) * 6];
            const float w00 = wp[0], w01 = wp[1], w10 = wp[2], w11 = wp[3], w20 = wp[4], w21 = wp[5];
            const float* A = ha + i * HH;
            const float* M = hm + i * HH;
            float wA[10], wM[10];
            wA[0] = (hb > 0) ? A[hb - 1] : 0.f;
            wM[0] = (hb > 0) ? M[hb - 1] : 0.f;
            #pragma unroll
            for (int t = 0; t < 8; t++) { wA[t + 1] = A[hb + t]; wM[t + 1] = M[hb + t]; }
            wA[9] = (hb + 8 < HH) ? A[hb + 8] : 0.f;
            wM[9] = (hb + 8 < HH) ? M[hb + 8] : 0.f;
            #pragma unroll
            for (int t = 0; t < 8; t++) {
                acc[t] += wA[t] * w00 + wM[t] * w01
                        + wA[t + 1] * w10 + wM[t + 1] * w11
                        + wA[t + 2] * w20 + wM[t + 2] * w21;
            }
        }

        float lm = -3.4e38f;
        #pragma unroll
        for (int t = 0; t < 8; t++) { acc[t] = fmaxf(acc[t], 0.f); lm = fmaxf(lm, acc[t]); }
        #pragma unroll
        for (int off = 1; off <= 4; off <<= 1) lm = fmaxf(lm, __shfl_xor_sync(0xffffffffu, lm, off));
        float ls = 0.f;
        #pragma unroll
        for (int t = 0; t < 8; t++) { acc[t] = __expf(acc[t] - lm); ls += acc[t]; }
        #pragma unroll
        for (int off = 1; off <= 4; off <<= 1) ls += __shfl_xor_sync(0xffffffffu, ls, off);
        const float inv = 1.0f / ls;
        #pragma unroll
        for (int t = 0; t < 8; t++) g_ph[(n * PC + o) * HH + hb + t] = acc[t] * inv;
    } else {
        // ---------------- pw: conv 2x3 pad(w)=1 + relu + softmax over w ----
        const int b2 = bid - 64;
        const int n  = b2 >> 2;
        const int og = b2 & 3;          // o group of 8

        float* wa = sm;                  // [32][512]
        float* wm = sm + PC * WW;        // [32][512]
        float* ww = sm + 2 * PC * WW;    // 8*32*6 = 1536

        {
            const float4* sa = reinterpret_cast<const float4*>(g_wavg + n * PC * WW);
            const float4* sx = reinterpret_cast<const float4*>(g_wmax + n * PC * WW);
            float4* da = reinterpret_cast<float4*>(wa);
            float4* dm = reinterpret_cast<float4*>(wm);
            for (int idx = tid; idx < PC * WW / 4; idx += 256) { da[idx] = sa[idx]; dm[idx] = sx[idx]; }
        }
        {
            const float* src = w_w + og * 8 * PC * 6;
            for (int idx = tid; idx < 8 * PC * 6; idx += 256) ww[idx] = src[idx];
        }
        __syncthreads();

        const int oo = tid >> 5;            // 0..7 within group
        const int o  = og * 8 + oo;
        const int j  = tid & 31;            // one warp per o

        float acc[16];
        const float bo = b_w[o];
        #pragma unroll
        for (int t = 0; t < 16; t++) acc[t] = bo;

        for (int i = 0; i < PC; i++) {
            const float* wp = &ww[(oo * PC + i) * 6];
            const float a0 = wp[0], a1 = wp[1], a2 = wp[2];
            const float m0 = wp[3], m1 = wp[4], m2 = wp[5];
            const float* A = wa + i * WW;
            const float* M = wm + i * WW;
            #pragma unroll
            for (int k = 0; k < 4; k++) {
                const int w0 = j * 4 + k * 128;
                float4 av = *reinterpret_cast<const float4*>(&A[w0]);
                float4 mv = *reinterpret_cast<const float4*>(&M[w0]);
                float am1 = (w0 > 0) ? A[w0 - 1] : 0.f;
                float mm1 = (w0 > 0) ? M[w0 - 1] : 0.f;
                float ap4 = (w0 + 4 < WW) ? A[w0 + 4] : 0.f;
                float mp4 = (w0 + 4 < WW) ? M[w0 + 4] : 0.f;
                acc[k*4+0] += am1 * a0 + av.x * a1 + av.y * a2 + mm1 * m0 + mv.x * m1 + mv.y * m2;
                acc[k*4+1] += av.x * a0 + av.y * a1 + av.z * a2 + mv.x * m0 + mv.y * m1 + mv.z * m2;
                acc[k*4+2] += av.y * a0 + av.z * a1 + av.w * a2 + mv.y * m0 + mv.z * m1 + mv.w * m2;
                acc[k*4+3] += av.z * a0 + av.w * a1 + ap4 * a2 + mv.z * m0 + mv.w * m1 + mp4 * m2;
            }
        }

        float lm = -3.4e38f;
        #pragma unroll
        for (int t = 0; t < 16; t++) { acc[t] = fmaxf(acc[t], 0.f); lm = fmaxf(lm, acc[t]); }
        #pragma unroll
        for (int off = 1; off <= 16; off <<= 1) lm = fmaxf(lm, __shfl_xor_sync(0xffffffffu, lm, off));
        float ls = 0.f;
        #pragma unroll
        for (int t = 0; t < 16; t++) { acc[t] = __expf(acc[t] - lm); ls += acc[t]; }
        #pragma unroll
        for (int off = 1; off <= 16; off <<= 1) ls += __shfl_xor_sync(0xffffffffu, ls, off);
        const float inv = 1.0f / ls;

        float* dst = g_pw + (n * PC + o) * WW;
        #pragma unroll
        for (int k = 0; k < 4; k++) {
            const int w0 = j * 4 + k * 128;
            float4 r;
            r.x = acc[k*4+0] * inv; r.y = acc[k*4+1] * inv;
            r.z = acc[k*4+2] * inv; r.w = acc[k*4+3] * inv;
            *reinterpret_cast<float4*>(&dst[w0]) = r;
        }
    }
}

// ---------------------------------------------------------------------------
// K4: apply. One CTA per (n, h-block of 4, w-half). 48KB smem -> 4 CTAs/SM.
// 256 threads, f32x2 packed FMA. dynamic smem: pw[32][256] + At4[4][32][32]
// ---------------------------------------------------------------------------
__global__ __launch_bounds__(256, 4) void k4_apply(const float* __restrict__ x,
                                                   const float* __restrict__ w_e,
                                                   const float* __restrict__ b_e,
                                                   float* __restrict__ out) {
    extern __shared__ float sm4[];
    float* pws = sm4;             // [32][256]
    float* At4 = sm4 + PC * WH;   // [4][c][o]
    __shared__ float phs[HB * PC];

    const int bid = blockIdx.x;
    const int n   = bid >> 5;
    const int hb  = (bid >> 1) & 15;   // h = hb*4 + hl
    const int wh  = bid & 1;           // w half
    const int tid = threadIdx.x;

    // stage pw half tile
    {
        const float4* pwg = reinterpret_cast<const float4*>(g_pw + n * PC * WW) + wh * (WH / 4);
        float4* pw4 = reinterpret_cast<float4*>(pws);
        for (int idx = tid; idx < PC * WH / 4; idx += 256) {
            const int c = idx >> 6, col = idx & 63;
            pw4[idx] = pwg[c * (WW / 4) + col];
        }
    }
    if (tid < HB * PC) {
        const int hl = tid >> 5, c = tid & 31;
        phs[tid] = g_ph[(n * PC + c) * HH + hb * HB + hl];
    }
    __syncthreads();

    for (int idx = tid; idx < HB * PC * PC; idx += 256) {
        const int hl = idx >> 10;
        const int c  = (idx >> 5) & 31;
        const int o  = idx & 31;
        At4[idx] = w_e[o * PC + c] * phs[hl * PC + c];
    }
    __syncthreads();

    const int ot = tid & 7;      // o-tile (varies fastest -> pw broadcast per phase)
    const int wt = tid >> 3;     // w-tile 0..31
    const int o0 = ot * 4;
    const int w0 = wt * 8;       // within half

    const float4 be = *reinterpret_cast<const float4*>(&b_e[o0]);
    const float bias[4] = { be.x, be.y, be.z, be.w };

    #pragma unroll 1
    for (int hl = 0; hl < HB; hl++) {
        const int h = hb * HB + hl;
        const float* At = At4 + hl * (PC * PC);

        u64 acc[4][4];
        #pragma unroll
        for (int oi = 0; oi < 4; oi++)
            #pragma unroll
            for (int wj = 0; wj < 4; wj++) acc[oi][wj] = 0ull;

        #pragma unroll 4
        for (int c = 0; c < PC; c++) {
            const float4 a = *reinterpret_cast<const float4*>(&At[c * PC + o0]);
            u64 av[4];
            av[0] = pk2(a.x, a.x); av[1] = pk2(a.y, a.y);
            av[2] = pk2(a.z, a.z); av[3] = pk2(a.w, a.w);
            const ulonglong2* pr = reinterpret_cast<const ulonglong2*>(&pws[c * WH + w0]);
            ulonglong2 q0 = pr[0], q1 = pr[1];
            u64 pp[4] = { q0.x, q0.y, q1.x, q1.y };
            #pragma unroll
            for (int oi = 0; oi < 4; oi++)
                #pragma unroll
                for (int wj = 0; wj < 4; wj++)
                    ffma2(acc[oi][wj], av[oi], pp[wj]);
        }

        #pragma unroll
        for (int oi = 0; oi < 4; oi++) {
            const int o = o0 + oi;
            const float bo = bias[oi];
            const size_t base = (((size_t)(n * PC + o)) * HH + h) * WW + wh * WH + w0;
            const float4* xin = reinterpret_cast<const float4*>(x + base);
            float4* op = reinterpret_cast<float4*>(out + base);
            #pragma unroll
            for (int q = 0; q < 2; q++) {
                float4 xv = xin[q];
                float t0, t1, t2, t3;
                upk2(acc[oi][2 * q],     t0, t1);
                upk2(acc[oi][2 * q + 1], t2, t3);
                float4 r;
                r.x = xv.x * (1.0f + sigf(t0 + bo));
                r.y = xv.y * (1.0f + sigf(t1 + bo));
                r.z = xv.z * (1.0f + sigf(t2 + bo));
                r.w = xv.w * (1.0f + sigf(t3 + bo));
                op[q] = r;
            }
        }
    }
}

extern "C" void kernel_launch(void* const* d_in, const int* in_sizes, int n_in,
                              void* d_out, int out_size) {
    const float* x   = (const float*)d_in[0];
    const float* w_h = (const float*)d_in[1];
    const float* b_h = (const float*)d_in[2];
    const float* w_w = (const float*)d_in[3];
    const float* b_w = (const float*)d_in[4];
    const float* w_e = (const float*)d_in[5];
    const float* b_e = (const float*)d_in[6];
    float* out = (float*)d_out;

    const int smem23 = (2 * PC * WW + 8 * PC * 6) * 4;   // 137216
    const int smem4  = (PC * WH + HB * PC * PC) * 4;     // 49152
    cudaFuncSetAttribute(k23,      cudaFuncAttributeMaxDynamicSharedMemorySize, smem23);
    cudaFuncSetAttribute(k4_apply, cudaFuncAttributeMaxDynamicSharedMemorySize, smem4);

    k1_stats<<<NP * PC, 256>>>(x);
    k23<<<64 + NP * 4, 256, smem23>>>(w_h, b_h, w_w, b_w);
    k4_apply<<<NP * 16 * 2, 256, smem4>>>(x, w_e, b_e, out);
}